// round 1
// baseline (speedup 1.0000x reference)
#include <cuda_runtime.h>

#define N 8192
#define THREADS 256
#define BLOCK_ROWS 8
#define ROWS_PER_ITER 4
#define NUM_BLOCKS (N / BLOCK_ROWS)   // 1024

__device__ double g_partials[NUM_BLOCKS];

__device__ __forceinline__ float fsqrt_approx(float x) {
    float r; asm("sqrt.approx.f32 %0, %1;" : "=f"(r) : "f"(x)); return r;
}
__device__ __forceinline__ float frcp_approx(float x) {
    float r; asm("rcp.approx.f32 %0, %1;" : "=f"(r) : "f"(x)); return r;
}

// one element: term = (dist!=0) ? ((|pj-pi| - dist)/dist)^2 : 0
__device__ __forceinline__ void accum_term(float& acc, float d,
                                           float pjx, float pjy,
                                           float pix, float piy) {
    float dx = pjx - pix;
    float dy = pjy - piy;
    float sq = fmaf(dy, dy, dx * dx);
    float pred = fsqrt_approx(sq);          // sqrt.approx(0) == 0 (diagonal safe)
    float e = pred - d;
    float q = e * frcp_approx(d);           // rcp.approx(0) = inf, masked below
    q = (d != 0.0f) ? q : 0.0f;
    acc = fmaf(q, q, acc);
}

extern __shared__ float4 s_pos4[];          // N/2 float4 = 64 KB (all of pos)

__global__ __launch_bounds__(THREADS)
void stress_kernel(const float2* __restrict__ pos,
                   const float*  __restrict__ dist) {
    // Stage pos into shared memory once per CTA (keeps pos off L2/HBM per element)
    const float4* pos4 = reinterpret_cast<const float4*>(pos);
    for (int t = threadIdx.x; t < N / 2; t += THREADS)
        s_pos4[t] = pos4[t];
    __syncthreads();

    const float2* s_pos2 = reinterpret_cast<const float2*>(s_pos4);
    const int row0 = blockIdx.x * BLOCK_ROWS;

    float acc = 0.0f;

    for (int r = 0; r < BLOCK_ROWS; r += ROWS_PER_ITER) {
        float pix[ROWS_PER_ITER], piy[ROWS_PER_ITER];
        #pragma unroll
        for (int k = 0; k < ROWS_PER_ITER; k++) {
            float2 p = s_pos2[row0 + r + k];
            pix[k] = p.x; piy[k] = p.y;
        }

        // each thread handles 4 consecutive columns per iteration, 4 rows deep
        #pragma unroll 2
        for (int j4 = threadIdx.x; j4 < N / 4; j4 += THREADS) {
            const int j = 4 * j4;

            // pos for columns j..j+3 from shared (2x LDS.128)
            float4 p01 = s_pos4[2 * j4];
            float4 p23 = s_pos4[2 * j4 + 1];

            // 4 independent streaming loads -> MLP 4
            float4 dv[ROWS_PER_ITER];
            #pragma unroll
            for (int k = 0; k < ROWS_PER_ITER; k++) {
                const float4* p = reinterpret_cast<const float4*>(
                    dist + (size_t)(row0 + r + k) * N + j);
                dv[k] = __ldcs(p);
            }

            #pragma unroll
            for (int k = 0; k < ROWS_PER_ITER; k++) {
                accum_term(acc, dv[k].x, p01.x, p01.y, pix[k], piy[k]);
                accum_term(acc, dv[k].y, p01.z, p01.w, pix[k], piy[k]);
                accum_term(acc, dv[k].z, p23.x, p23.y, pix[k], piy[k]);
                accum_term(acc, dv[k].w, p23.z, p23.w, pix[k], piy[k]);
            }
        }
    }

    // Deterministic block reduction (fixed shuffle tree)
    #pragma unroll
    for (int o = 16; o > 0; o >>= 1)
        acc += __shfl_down_sync(0xffffffffu, acc, o);

    __shared__ float warpsum[THREADS / 32];
    const int lane = threadIdx.x & 31;
    const int wid  = threadIdx.x >> 5;
    if (lane == 0) warpsum[wid] = acc;
    __syncthreads();

    if (wid == 0) {
        float v = (lane < THREADS / 32) ? warpsum[lane] : 0.0f;
        #pragma unroll
        for (int o = 4; o > 0; o >>= 1)
            v += __shfl_down_sync(0xffu, v, o);
        if (lane == 0) g_partials[blockIdx.x] = (double)v;
    }
}

__global__ void reduce_kernel(float* __restrict__ out) {
    __shared__ double s[NUM_BLOCKS];
    s[threadIdx.x] = g_partials[threadIdx.x];
    __syncthreads();
    #pragma unroll
    for (int o = NUM_BLOCKS / 2; o > 0; o >>= 1) {
        if ((int)threadIdx.x < o) s[threadIdx.x] += s[threadIdx.x + o];
        __syncthreads();
    }
    if (threadIdx.x == 0) out[0] = (float)s[0];
}

extern "C" void kernel_launch(void* const* d_in, const int* in_sizes, int n_in,
                              void* d_out, int out_size) {
    const float* a = (const float*)d_in[0];
    const float* b = (const float*)d_in[1];
    const float2* pos;
    const float*  dist;
    if (in_sizes[0] < in_sizes[1]) { pos = (const float2*)a; dist = b; }
    else                           { pos = (const float2*)b; dist = a; }

    cudaFuncSetAttribute(stress_kernel,
                         cudaFuncAttributeMaxDynamicSharedMemorySize, 65536);

    stress_kernel<<<NUM_BLOCKS, THREADS, 65536>>>(pos, dist);
    reduce_kernel<<<1, NUM_BLOCKS>>>((float*)d_out);
}

// round 2
// speedup vs baseline: 1.6661x; 1.6661x over previous
#include <cuda_runtime.h>

#define N 8192
#define THREADS 256
#define ROWS_PER_CTA 2
#define NUM_BLOCKS (N / ROWS_PER_CTA)            // 4096
#define COLS_PER_THREAD 8                         // two float4 per row
#define ITERS (N / (THREADS * COLS_PER_THREAD))   // 4

__device__ float        g_partials[NUM_BLOCKS];
__device__ unsigned int g_count = 0;

__device__ __forceinline__ float fsqrt_approx(float x) {
    float r; asm("sqrt.approx.f32 %0, %1;" : "=f"(r) : "f"(x)); return r;
}
__device__ __forceinline__ float frcp_approx(float x) {
    float r; asm("rcp.approx.f32 %0, %1;" : "=f"(r) : "f"(x)); return r;
}

// term = (d != 0) ? ((|pj-pi| - d)/d)^2 : 0
__device__ __forceinline__ void accum_term(float& acc, float d,
                                           float pjx, float pjy,
                                           float pix, float piy) {
    float dx = pjx - pix;
    float dy = pjy - piy;
    float sq = fmaf(dy, dy, dx * dx);
    float pred = fsqrt_approx(sq);        // sqrt.approx(0) == 0 (diagonal safe)
    float e = pred - d;
    float q = e * frcp_approx(d);         // rcp.approx(0) = inf, masked next
    q = (d != 0.0f) ? q : 0.0f;
    acc = fmaf(q, q, acc);
}

__global__ __launch_bounds__(THREADS)
void stress_kernel(const float4* __restrict__ pos4,   // [N/2] float4 = [N] float2
                   const float*  __restrict__ dist,
                   float* __restrict__ out) {
    const int row0 = blockIdx.x * ROWS_PER_CTA;

    // row positions (uniform per CTA, L1/const path)
    const float2* pos2 = reinterpret_cast<const float2*>(pos4);
    float2 pi0 = __ldg(&pos2[row0]);
    float2 pi1 = __ldg(&pos2[row0 + 1]);

    const float* drow0 = dist + (size_t)row0 * N;
    const float* drow1 = drow0 + N;

    float acc = 0.0f;

    #pragma unroll 2
    for (int u = 0; u < ITERS; u++) {
        const int idx8 = u * THREADS + threadIdx.x;   // unit of 8 columns
        const int col  = idx8 * COLS_PER_THREAD;

        // 4 independent streaming loads (MLP >= 4 per thread, >=8 with unroll 2)
        float4 d00 = __ldcs(reinterpret_cast<const float4*>(drow0 + col));
        float4 d01 = __ldcs(reinterpret_cast<const float4*>(drow0 + col + 4));
        float4 d10 = __ldcs(reinterpret_cast<const float4*>(drow1 + col));
        float4 d11 = __ldcs(reinterpret_cast<const float4*>(drow1 + col + 4));

        // column positions from L1-resident pos (64 KB fits in L1)
        float4 p01 = __ldg(&pos4[idx8 * 4 + 0]);   // cols col..col+1
        float4 p23 = __ldg(&pos4[idx8 * 4 + 1]);   // cols col+2..col+3
        float4 p45 = __ldg(&pos4[idx8 * 4 + 2]);   // cols col+4..col+5
        float4 p67 = __ldg(&pos4[idx8 * 4 + 3]);   // cols col+6..col+7

        accum_term(acc, d00.x, p01.x, p01.y, pi0.x, pi0.y);
        accum_term(acc, d00.y, p01.z, p01.w, pi0.x, pi0.y);
        accum_term(acc, d00.z, p23.x, p23.y, pi0.x, pi0.y);
        accum_term(acc, d00.w, p23.z, p23.w, pi0.x, pi0.y);
        accum_term(acc, d01.x, p45.x, p45.y, pi0.x, pi0.y);
        accum_term(acc, d01.y, p45.z, p45.w, pi0.x, pi0.y);
        accum_term(acc, d01.z, p67.x, p67.y, pi0.x, pi0.y);
        accum_term(acc, d01.w, p67.z, p67.w, pi0.x, pi0.y);

        accum_term(acc, d10.x, p01.x, p01.y, pi1.x, pi1.y);
        accum_term(acc, d10.y, p01.z, p01.w, pi1.x, pi1.y);
        accum_term(acc, d10.z, p23.x, p23.y, pi1.x, pi1.y);
        accum_term(acc, d10.w, p23.z, p23.w, pi1.x, pi1.y);
        accum_term(acc, d11.x, p45.x, p45.y, pi1.x, pi1.y);
        accum_term(acc, d11.y, p45.z, p45.w, pi1.x, pi1.y);
        accum_term(acc, d11.z, p67.x, p67.y, pi1.x, pi1.y);
        accum_term(acc, d11.w, p67.z, p67.w, pi1.x, pi1.y);
    }

    // intra-CTA deterministic reduction
    #pragma unroll
    for (int o = 16; o > 0; o >>= 1)
        acc += __shfl_down_sync(0xffffffffu, acc, o);

    __shared__ float warpsum[THREADS / 32];
    const int lane = threadIdx.x & 31;
    const int wid  = threadIdx.x >> 5;
    if (lane == 0) warpsum[wid] = acc;
    __syncthreads();

    __shared__ bool is_last;
    if (threadIdx.x == 0) {
        float v = 0.0f;
        #pragma unroll
        for (int w = 0; w < THREADS / 32; w++) v += warpsum[w];
        g_partials[blockIdx.x] = v;
        __threadfence();
        unsigned int prev = atomicAdd(&g_count, 1u);
        is_last = (prev == NUM_BLOCKS - 1);
    }
    __syncthreads();

    // last CTA: deterministic final reduction over 4096 partials
    if (is_last) {
        __shared__ double s[THREADS];
        double t = 0.0;
        #pragma unroll
        for (int k = 0; k < NUM_BLOCKS / THREADS; k++)
            t += (double)g_partials[threadIdx.x * (NUM_BLOCKS / THREADS) + k];
        s[threadIdx.x] = t;
        __syncthreads();
        #pragma unroll
        for (int o = THREADS / 2; o > 0; o >>= 1) {
            if ((int)threadIdx.x < o) s[threadIdx.x] += s[threadIdx.x + o];
            __syncthreads();
        }
        if (threadIdx.x == 0) {
            out[0] = (float)s[0];
            g_count = 0;                 // reset for next (graph-replayed) launch
        }
    }
}

extern "C" void kernel_launch(void* const* d_in, const int* in_sizes, int n_in,
                              void* d_out, int out_size) {
    const float* a = (const float*)d_in[0];
    const float* b = (const float*)d_in[1];
    const float4* pos4;
    const float*  dist;
    if (in_sizes[0] < in_sizes[1]) { pos4 = (const float4*)a; dist = b; }
    else                           { pos4 = (const float4*)b; dist = a; }

    stress_kernel<<<NUM_BLOCKS, THREADS>>>(pos4, dist, (float*)d_out);
}

// round 3
// speedup vs baseline: 1.7231x; 1.0342x over previous
#include <cuda_runtime.h>

#define N 8192
#define THREADS 256
#define ROWS_PER_CTA 4
#define NUM_BLOCKS (N / ROWS_PER_CTA)             // 2048
#define COLS_PER_THREAD 8                          // two float4 per row
#define ITERS (N / (THREADS * COLS_PER_THREAD))    // 4

__device__ float        g_partials[NUM_BLOCKS];
__device__ unsigned int g_count = 0;

__device__ __forceinline__ float fsqrt_approx(float x) {
    float r; asm("sqrt.approx.f32 %0, %1;" : "=f"(r) : "f"(x)); return r;
}
__device__ __forceinline__ float frcp_approx(float x) {
    float r; asm("rcp.approx.f32 %0, %1;" : "=f"(r) : "f"(x)); return r;
}

// term = (d != 0) ? ((|pj-pi| - d)/d)^2 : 0
__device__ __forceinline__ void accum_term(float& acc, float d,
                                           float pjx, float pjy,
                                           float npix, float npiy) {
    float dx = pjx + npix;                 // npix = -pix
    float dy = pjy + npiy;
    float sq = fmaf(dy, dy, dx * dx);
    float pred = fsqrt_approx(sq);         // sqrt.approx(0) == 0 (diagonal safe)
    float e = pred - d;
    float q = e * frcp_approx(d);          // rcp.approx(0) = inf, masked next
    q = (d != 0.0f) ? q : 0.0f;
    acc = fmaf(q, q, acc);
}

__global__ __launch_bounds__(THREADS, 3)
void stress_kernel(const float4* __restrict__ pos4,   // [N/2] float4 = [N] float2
                   const float*  __restrict__ dist,
                   float* __restrict__ out) {
    const int row0 = blockIdx.x * ROWS_PER_CTA;

    // negated row positions (uniform per CTA)
    const float2* pos2 = reinterpret_cast<const float2*>(pos4);
    float npx[ROWS_PER_CTA], npy[ROWS_PER_CTA];
    #pragma unroll
    for (int k = 0; k < ROWS_PER_CTA; k++) {
        float2 p = __ldg(&pos2[row0 + k]);
        npx[k] = -p.x; npy[k] = -p.y;
    }

    const float* dr0 = dist + (size_t)row0 * N;
    const float* dr1 = dr0 + N;
    const float* dr2 = dr1 + N;
    const float* dr3 = dr2 + N;

    float acc0 = 0.0f, acc1 = 0.0f;

    for (int u = 0; u < ITERS; u++) {
        const int idx8 = u * THREADS + threadIdx.x;   // unit of 8 columns
        const int col  = idx8 * COLS_PER_THREAD;

        // 8 independent streaming loads -> MLP 8, 4 base addresses (+16B imm)
        float4 d0a = __ldcs(reinterpret_cast<const float4*>(dr0 + col));
        float4 d0b = __ldcs(reinterpret_cast<const float4*>(dr0 + col + 4));
        float4 d1a = __ldcs(reinterpret_cast<const float4*>(dr1 + col));
        float4 d1b = __ldcs(reinterpret_cast<const float4*>(dr1 + col + 4));
        float4 d2a = __ldcs(reinterpret_cast<const float4*>(dr2 + col));
        float4 d2b = __ldcs(reinterpret_cast<const float4*>(dr2 + col + 4));
        float4 d3a = __ldcs(reinterpret_cast<const float4*>(dr3 + col));
        float4 d3b = __ldcs(reinterpret_cast<const float4*>(dr3 + col + 4));

        // column positions (L1-resident, one base address, imm offsets)
        float4 p01 = __ldg(&pos4[idx8 * 4 + 0]);
        float4 p23 = __ldg(&pos4[idx8 * 4 + 1]);
        float4 p45 = __ldg(&pos4[idx8 * 4 + 2]);
        float4 p67 = __ldg(&pos4[idx8 * 4 + 3]);

        accum_term(acc0, d0a.x, p01.x, p01.y, npx[0], npy[0]);
        accum_term(acc0, d0a.y, p01.z, p01.w, npx[0], npy[0]);
        accum_term(acc0, d0a.z, p23.x, p23.y, npx[0], npy[0]);
        accum_term(acc0, d0a.w, p23.z, p23.w, npx[0], npy[0]);
        accum_term(acc0, d0b.x, p45.x, p45.y, npx[0], npy[0]);
        accum_term(acc0, d0b.y, p45.z, p45.w, npx[0], npy[0]);
        accum_term(acc0, d0b.z, p67.x, p67.y, npx[0], npy[0]);
        accum_term(acc0, d0b.w, p67.z, p67.w, npx[0], npy[0]);

        accum_term(acc1, d1a.x, p01.x, p01.y, npx[1], npy[1]);
        accum_term(acc1, d1a.y, p01.z, p01.w, npx[1], npy[1]);
        accum_term(acc1, d1a.z, p23.x, p23.y, npx[1], npy[1]);
        accum_term(acc1, d1a.w, p23.z, p23.w, npx[1], npy[1]);
        accum_term(acc1, d1b.x, p45.x, p45.y, npx[1], npy[1]);
        accum_term(acc1, d1b.y, p45.z, p45.w, npx[1], npy[1]);
        accum_term(acc1, d1b.z, p67.x, p67.y, npx[1], npy[1]);
        accum_term(acc1, d1b.w, p67.z, p67.w, npx[1], npy[1]);

        accum_term(acc0, d2a.x, p01.x, p01.y, npx[2], npy[2]);
        accum_term(acc0, d2a.y, p01.z, p01.w, npx[2], npy[2]);
        accum_term(acc0, d2a.z, p23.x, p23.y, npx[2], npy[2]);
        accum_term(acc0, d2a.w, p23.z, p23.w, npx[2], npy[2]);
        accum_term(acc0, d2b.x, p45.x, p45.y, npx[2], npy[2]);
        accum_term(acc0, d2b.y, p45.z, p45.w, npx[2], npy[2]);
        accum_term(acc0, d2b.z, p67.x, p67.y, npx[2], npy[2]);
        accum_term(acc0, d2b.w, p67.z, p67.w, npx[2], npy[2]);

        accum_term(acc1, d3a.x, p01.x, p01.y, npx[3], npy[3]);
        accum_term(acc1, d3a.y, p01.z, p01.w, npx[3], npy[3]);
        accum_term(acc1, d3a.z, p23.x, p23.y, npx[3], npy[3]);
        accum_term(acc1, d3a.w, p23.z, p23.w, npx[3], npy[3]);
        accum_term(acc1, d3b.x, p45.x, p45.y, npx[3], npy[3]);
        accum_term(acc1, d3b.y, p45.z, p45.w, npx[3], npy[3]);
        accum_term(acc1, d3b.z, p67.x, p67.y, npx[3], npy[3]);
        accum_term(acc1, d3b.w, p67.z, p67.w, npx[3], npy[3]);
    }

    float acc = acc0 + acc1;

    // intra-CTA deterministic reduction
    #pragma unroll
    for (int o = 16; o > 0; o >>= 1)
        acc += __shfl_down_sync(0xffffffffu, acc, o);

    __shared__ float warpsum[THREADS / 32];
    const int lane = threadIdx.x & 31;
    const int wid  = threadIdx.x >> 5;
    if (lane == 0) warpsum[wid] = acc;
    __syncthreads();

    __shared__ bool is_last;
    if (threadIdx.x == 0) {
        float v = 0.0f;
        #pragma unroll
        for (int w = 0; w < THREADS / 32; w++) v += warpsum[w];
        g_partials[blockIdx.x] = v;
        __threadfence();
        unsigned int prev = atomicAdd(&g_count, 1u);
        is_last = (prev == NUM_BLOCKS - 1);
    }
    __syncthreads();

    // last CTA: deterministic final reduction over 2048 partials
    if (is_last) {
        __shared__ double s[THREADS];
        double t = 0.0;
        #pragma unroll
        for (int k = 0; k < NUM_BLOCKS / THREADS; k++)
            t += (double)g_partials[threadIdx.x * (NUM_BLOCKS / THREADS) + k];
        s[threadIdx.x] = t;
        __syncthreads();
        #pragma unroll
        for (int o = THREADS / 2; o > 0; o >>= 1) {
            if ((int)threadIdx.x < o) s[threadIdx.x] += s[threadIdx.x + o];
            __syncthreads();
        }
        if (threadIdx.x == 0) {
            out[0] = (float)s[0];
            g_count = 0;                 // reset for next graph replay
        }
    }
}

extern "C" void kernel_launch(void* const* d_in, const int* in_sizes, int n_in,
                              void* d_out, int out_size) {
    const float* a = (const float*)d_in[0];
    const float* b = (const float*)d_in[1];
    const float4* pos4;
    const float*  dist;
    if (in_sizes[0] < in_sizes[1]) { pos4 = (const float4*)a; dist = b; }
    else                           { pos4 = (const float4*)b; dist = a; }

    stress_kernel<<<NUM_BLOCKS, THREADS>>>(pos4, dist, (float*)d_out);
}

// round 4
// speedup vs baseline: 1.8636x; 1.0815x over previous
#include <cuda_runtime.h>

#define N 8192
#define THREADS 256
#define ROWS_PER_CTA 4
#define NUM_BLOCKS (N / ROWS_PER_CTA)              // 2048
#define COLS_PER_THREAD 4
#define ITERS (N / (THREADS * COLS_PER_THREAD))    // 8

typedef unsigned long long ull;
union f2u { float2 f; ull u; };

__device__ float        g_xs[N];
__device__ float        g_ys[N];
__device__ float        g_partials[NUM_BLOCKS];
__device__ unsigned int g_count = 0;

__device__ __forceinline__ ull f2add(ull a, ull b) {
    ull c; asm("add.rn.f32x2 %0, %1, %2;" : "=l"(c) : "l"(a), "l"(b)); return c;
}
__device__ __forceinline__ ull f2mul(ull a, ull b) {
    ull c; asm("mul.rn.f32x2 %0, %1, %2;" : "=l"(c) : "l"(a), "l"(b)); return c;
}
__device__ __forceinline__ ull f2fma(ull a, ull b, ull c) {
    ull d; asm("fma.rn.f32x2 %0, %1, %2, %3;" : "=l"(d) : "l"(a), "l"(b), "l"(c)); return d;
}
__device__ __forceinline__ float fsqrt_a(float x) {
    float r; asm("sqrt.approx.f32 %0, %1;" : "=f"(r) : "f"(x)); return r;
}
__device__ __forceinline__ float frcp_a(float x) {
    float r; asm("rcp.approx.f32 %0, %1;" : "=f"(r) : "f"(x)); return r;
}

// SoA pre-pass: pos [N,2] AoS -> g_xs / g_ys (enables packed column pairs)
__global__ void soa_kernel(const float2* __restrict__ pos2) {
    int i = blockIdx.x * blockDim.x + threadIdx.x;
    float2 p = pos2[i];
    g_xs[i] = p.x;
    g_ys[i] = p.y;
}

__global__ __launch_bounds__(THREADS)
void stress_kernel(const float2* __restrict__ pos2,
                   const float*  __restrict__ dist,
                   float* __restrict__ out) {
    const int row0 = blockIdx.x * ROWS_PER_CTA;

    // broadcast pairs of negated row positions
    f2u nx[ROWS_PER_CTA], ny[ROWS_PER_CTA];
    #pragma unroll
    for (int k = 0; k < ROWS_PER_CTA; k++) {
        float2 p = __ldg(&pos2[row0 + k]);
        nx[k].f.x = -p.x; nx[k].f.y = -p.x;
        ny[k].f.x = -p.y; ny[k].f.y = -p.y;
    }

    const float* dr0 = dist + (size_t)row0 * N;
    const float* dr1 = dr0 + N;
    const float* dr2 = dr1 + N;
    const float* dr3 = dr2 + N;

    f2u acc01, acc23;
    acc01.f.x = 0.f; acc01.f.y = 0.f;
    acc23.f.x = 0.f; acc23.f.y = 0.f;
    float acc_s = 0.f;                       // scalar safe-path accumulator

    f2u NEG1; NEG1.f.x = -1.f; NEG1.f.y = -1.f;

    for (int it = 0; it < ITERS; it++) {
        const int j = (it * THREADS + threadIdx.x) * COLS_PER_THREAD;

        float4 x4 = __ldg(reinterpret_cast<const float4*>(&g_xs[j]));
        float4 y4 = __ldg(reinterpret_cast<const float4*>(&g_ys[j]));

        float4 d0 = __ldcs(reinterpret_cast<const float4*>(dr0 + j));
        float4 d1 = __ldcs(reinterpret_cast<const float4*>(dr1 + j));
        float4 d2 = __ldcs(reinterpret_cast<const float4*>(dr2 + j));
        float4 d3 = __ldcs(reinterpret_cast<const float4*>(dr3 + j));

        // zero-detection over all 16 dist values (d >= 0 for this data; a
        // -0.0 would make mn <= 0 and fall to the safe path, still correct)
        float m0 = fminf(fminf(d0.x, d0.y), fminf(d0.z, d0.w));
        float m1 = fminf(fminf(d1.x, d1.y), fminf(d1.z, d1.w));
        float m2 = fminf(fminf(d2.x, d2.y), fminf(d2.z, d2.w));
        float m3 = fminf(fminf(d3.x, d3.y), fminf(d3.z, d3.w));
        float mn = fminf(fminf(m0, m1), fminf(m2, m3));

        if (mn > 0.0f) {
            // packed column pairs
            f2u xa, xb, ya, yb;
            xa.f.x = x4.x; xa.f.y = x4.y;  xb.f.x = x4.z; xb.f.y = x4.w;
            ya.f.x = y4.x; ya.f.y = y4.y;  yb.f.x = y4.z; yb.f.y = y4.w;

            auto grp = [&](const float4& d, ull nxp, ull nyp) {
                // Montgomery batched reciprocal: 1 MUFU.RCP per 4 elements
                float p01   = d.x * d.y;
                float p012  = p01 * d.z;
                float p0123 = p012 * d.w;
                float R  = frcp_a(p0123);
                float i3 = p012 * R;  float R3 = R  * d.w;
                float i2 = p01  * R3; float R2 = R3 * d.z;
                float i1 = d.x  * R2; float i0 = d.y * R2;
                f2u iv01; iv01.f.x = i0; iv01.f.y = i1;
                f2u iv23; iv23.f.x = i2; iv23.f.y = i3;
                f2u dpa;  dpa.f.x = d.x; dpa.f.y = d.y;   (void)dpa;

                // pair A: columns j, j+1
                ull dxa = f2add(xa.u, nxp);
                ull dya = f2add(ya.u, nyp);
                ull sqa = f2fma(dya, dya, f2mul(dxa, dxa));
                f2u sa; sa.u = sqa;
                f2u pa; pa.f.x = fsqrt_a(sa.f.x); pa.f.y = fsqrt_a(sa.f.y);
                ull uaa = f2fma(pa.u, iv01.u, NEG1.u);   // pred/d - 1
                acc01.u = f2fma(uaa, uaa, acc01.u);

                // pair B: columns j+2, j+3
                ull dxb = f2add(xb.u, nxp);
                ull dyb = f2add(yb.u, nyp);
                ull sqb = f2fma(dyb, dyb, f2mul(dxb, dxb));
                f2u sb; sb.u = sqb;
                f2u pb; pb.f.x = fsqrt_a(sb.f.x); pb.f.y = fsqrt_a(sb.f.y);
                ull ubb = f2fma(pb.u, iv23.u, NEG1.u);
                acc23.u = f2fma(ubb, ubb, acc23.u);
            };

            grp(d0, nx[0].u, ny[0].u);
            grp(d1, nx[1].u, ny[1].u);
            grp(d2, nx[2].u, ny[2].u);
            grp(d3, nx[3].u, ny[3].u);
        } else {
            // exact scalar fallback (rare: group contains a zero distance)
            auto safe = [&](float d, float xj, float yj, float px, float py) {
                float dx = xj + px, dy = yj + py;
                float sq = fmaf(dy, dy, dx * dx);
                float pr = fsqrt_a(sq);
                float q  = (pr - d) * frcp_a(d);
                q = (d != 0.0f) ? q : 0.0f;
                acc_s = fmaf(q, q, acc_s);
            };
            const float4 dd[4] = {d0, d1, d2, d3};
            #pragma unroll
            for (int k = 0; k < ROWS_PER_CTA; k++) {
                safe(dd[k].x, x4.x, y4.x, nx[k].f.x, ny[k].f.x);
                safe(dd[k].y, x4.y, y4.y, nx[k].f.x, ny[k].f.x);
                safe(dd[k].z, x4.z, y4.z, nx[k].f.x, ny[k].f.x);
                safe(dd[k].w, x4.w, y4.w, nx[k].f.x, ny[k].f.x);
            }
        }
    }

    float acc = (acc01.f.x + acc01.f.y) + (acc23.f.x + acc23.f.y) + acc_s;

    // intra-CTA deterministic reduction
    #pragma unroll
    for (int o = 16; o > 0; o >>= 1)
        acc += __shfl_down_sync(0xffffffffu, acc, o);

    __shared__ float warpsum[THREADS / 32];
    const int lane = threadIdx.x & 31;
    const int wid  = threadIdx.x >> 5;
    if (lane == 0) warpsum[wid] = acc;
    __syncthreads();

    __shared__ bool is_last;
    if (threadIdx.x == 0) {
        float v = 0.0f;
        #pragma unroll
        for (int w = 0; w < THREADS / 32; w++) v += warpsum[w];
        g_partials[blockIdx.x] = v;
        __threadfence();
        unsigned int prev = atomicAdd(&g_count, 1u);
        is_last = (prev == NUM_BLOCKS - 1);
    }
    __syncthreads();

    if (is_last) {
        __shared__ double s[THREADS];
        double t = 0.0;
        #pragma unroll
        for (int k = 0; k < NUM_BLOCKS / THREADS; k++)
            t += (double)g_partials[threadIdx.x * (NUM_BLOCKS / THREADS) + k];
        s[threadIdx.x] = t;
        __syncthreads();
        #pragma unroll
        for (int o = THREADS / 2; o > 0; o >>= 1) {
            if ((int)threadIdx.x < o) s[threadIdx.x] += s[threadIdx.x + o];
            __syncthreads();
        }
        if (threadIdx.x == 0) {
            out[0] = (float)s[0];
            g_count = 0;                 // reset for next graph replay
        }
    }
}

extern "C" void kernel_launch(void* const* d_in, const int* in_sizes, int n_in,
                              void* d_out, int out_size) {
    const float* a = (const float*)d_in[0];
    const float* b = (const float*)d_in[1];
    const float2* pos2;
    const float*  dist;
    if (in_sizes[0] < in_sizes[1]) { pos2 = (const float2*)a; dist = b; }
    else                           { pos2 = (const float2*)b; dist = a; }

    soa_kernel<<<N / 256, 256>>>(pos2);
    stress_kernel<<<NUM_BLOCKS, THREADS>>>(pos2, dist, (float*)d_out);
}

// round 5
// speedup vs baseline: 1.9190x; 1.0298x over previous
#include <cuda_runtime.h>

#define N 8192
#define THREADS 256
#define ROWS_PER_CTA 4
#define NUM_BLOCKS (N / ROWS_PER_CTA)              // 2048
#define COLS_PER_THREAD 4
#define ITERS (N / (THREADS * COLS_PER_THREAD))    // 8

typedef unsigned long long ull;
union f2u { float2 f; ull u; };

__device__ float        g_xs[N];
__device__ float        g_ys[N];
__device__ float        g_partials[NUM_BLOCKS];
__device__ unsigned int g_count = 0;

__device__ __forceinline__ ull f2add(ull a, ull b) {
    ull c; asm("add.rn.f32x2 %0, %1, %2;" : "=l"(c) : "l"(a), "l"(b)); return c;
}
__device__ __forceinline__ ull f2mul(ull a, ull b) {
    ull c; asm("mul.rn.f32x2 %0, %1, %2;" : "=l"(c) : "l"(a), "l"(b)); return c;
}
__device__ __forceinline__ ull f2fma(ull a, ull b, ull c) {
    ull d; asm("fma.rn.f32x2 %0, %1, %2, %3;" : "=l"(d) : "l"(a), "l"(b), "l"(c)); return d;
}
__device__ __forceinline__ float fsqrt_a(float x) {
    float r; asm("sqrt.approx.f32 %0, %1;" : "=f"(r) : "f"(x)); return r;
}
__device__ __forceinline__ float frcp_a(float x) {
    float r; asm("rcp.approx.f32 %0, %1;" : "=f"(r) : "f"(x)); return r;
}

// SoA pre-pass: pos [N,2] AoS -> g_xs / g_ys
__global__ void soa_kernel(const float2* __restrict__ pos2) {
    int i = blockIdx.x * blockDim.x + threadIdx.x;
    float2 p = pos2[i];
    g_xs[i] = p.x;
    g_ys[i] = p.y;
}

__global__ __launch_bounds__(THREADS, 4)
void stress_kernel(const float2* __restrict__ pos2,
                   const float*  __restrict__ dist,
                   float* __restrict__ out) {
    const int row0 = blockIdx.x * ROWS_PER_CTA;

    f2u nx[ROWS_PER_CTA], ny[ROWS_PER_CTA];
    #pragma unroll
    for (int k = 0; k < ROWS_PER_CTA; k++) {
        float2 p = __ldg(&pos2[row0 + k]);
        nx[k].f.x = -p.x; nx[k].f.y = -p.x;
        ny[k].f.x = -p.y; ny[k].f.y = -p.y;
    }

    const float* dr0 = dist + (size_t)row0 * N;
    const float* dr1 = dr0 + N;
    const float* dr2 = dr1 + N;
    const float* dr3 = dr2 + N;

    f2u acc01, acc23;
    acc01.f.x = 0.f; acc01.f.y = 0.f;
    acc23.f.x = 0.f; acc23.f.y = 0.f;
    float acc_s = 0.f;

    f2u NEG1; NEG1.f.x = -1.f; NEG1.f.y = -1.f;

    // ---- software pipeline: prefetch iteration 0 ----
    int j = threadIdx.x * COLS_PER_THREAD;
    float4 x4 = __ldg(reinterpret_cast<const float4*>(&g_xs[j]));
    float4 y4 = __ldg(reinterpret_cast<const float4*>(&g_ys[j]));
    float4 d0 = __ldcs(reinterpret_cast<const float4*>(dr0 + j));
    float4 d1 = __ldcs(reinterpret_cast<const float4*>(dr1 + j));
    float4 d2 = __ldcs(reinterpret_cast<const float4*>(dr2 + j));
    float4 d3 = __ldcs(reinterpret_cast<const float4*>(dr3 + j));

    #pragma unroll
    for (int it = 0; it < ITERS; it++) {
        // prefetch next tile while current math runs
        float4 nx4, ny4, e0, e1, e2, e3;
        if (it + 1 < ITERS) {
            const int jn = ((it + 1) * THREADS + threadIdx.x) * COLS_PER_THREAD;
            nx4 = __ldg(reinterpret_cast<const float4*>(&g_xs[jn]));
            ny4 = __ldg(reinterpret_cast<const float4*>(&g_ys[jn]));
            e0  = __ldcs(reinterpret_cast<const float4*>(dr0 + jn));
            e1  = __ldcs(reinterpret_cast<const float4*>(dr1 + jn));
            e2  = __ldcs(reinterpret_cast<const float4*>(dr2 + jn));
            e3  = __ldcs(reinterpret_cast<const float4*>(dr3 + jn));
        }

        float m0 = fminf(fminf(d0.x, d0.y), fminf(d0.z, d0.w));
        float m1 = fminf(fminf(d1.x, d1.y), fminf(d1.z, d1.w));
        float m2 = fminf(fminf(d2.x, d2.y), fminf(d2.z, d2.w));
        float m3 = fminf(fminf(d3.x, d3.y), fminf(d3.z, d3.w));
        float mn = fminf(fminf(m0, m1), fminf(m2, m3));

        if (mn > 0.0f) {
            f2u xa, xb, ya, yb;
            xa.f.x = x4.x; xa.f.y = x4.y;  xb.f.x = x4.z; xb.f.y = x4.w;
            ya.f.x = y4.x; ya.f.y = y4.y;  yb.f.x = y4.z; yb.f.y = y4.w;

            auto grp = [&](const float4& d, ull nxp, ull nyp) {
                // Montgomery batched reciprocal: 1 MUFU.RCP per 4 elements
                float p01   = d.x * d.y;
                float p012  = p01 * d.z;
                float p0123 = p012 * d.w;
                float R  = frcp_a(p0123);
                float i3 = p012 * R;  float R3 = R  * d.w;
                float i2 = p01  * R3; float R2 = R3 * d.z;
                float i1 = d.x  * R2; float i0 = d.y * R2;
                f2u iv01; iv01.f.x = i0; iv01.f.y = i1;
                f2u iv23; iv23.f.x = i2; iv23.f.y = i3;

                ull dxa = f2add(xa.u, nxp);
                ull dya = f2add(ya.u, nyp);
                ull sqa = f2fma(dya, dya, f2mul(dxa, dxa));
                f2u sa; sa.u = sqa;
                f2u pa; pa.f.x = fsqrt_a(sa.f.x); pa.f.y = fsqrt_a(sa.f.y);
                ull uaa = f2fma(pa.u, iv01.u, NEG1.u);     // pred/d - 1
                acc01.u = f2fma(uaa, uaa, acc01.u);

                ull dxb = f2add(xb.u, nxp);
                ull dyb = f2add(yb.u, nyp);
                ull sqb = f2fma(dyb, dyb, f2mul(dxb, dxb));
                f2u sb; sb.u = sqb;
                f2u pb; pb.f.x = fsqrt_a(sb.f.x); pb.f.y = fsqrt_a(sb.f.y);
                ull ubb = f2fma(pb.u, iv23.u, NEG1.u);
                acc23.u = f2fma(ubb, ubb, acc23.u);
            };

            grp(d0, nx[0].u, ny[0].u);
            grp(d1, nx[1].u, ny[1].u);
            grp(d2, nx[2].u, ny[2].u);
            grp(d3, nx[3].u, ny[3].u);
        } else {
            // exact scalar fallback (rare: group contains a zero distance)
            auto safe = [&](float d, float xj, float yj, float px, float py) {
                float dx = xj + px, dy = yj + py;
                float sq = fmaf(dy, dy, dx * dx);
                float pr = fsqrt_a(sq);
                float q  = (pr - d) * frcp_a(d);
                q = (d != 0.0f) ? q : 0.0f;
                acc_s = fmaf(q, q, acc_s);
            };
            const float4 dd[4] = {d0, d1, d2, d3};
            #pragma unroll
            for (int k = 0; k < ROWS_PER_CTA; k++) {
                safe(dd[k].x, x4.x, y4.x, nx[k].f.x, ny[k].f.x);
                safe(dd[k].y, x4.y, y4.y, nx[k].f.x, ny[k].f.x);
                safe(dd[k].z, x4.z, y4.z, nx[k].f.x, ny[k].f.x);
                safe(dd[k].w, x4.w, y4.w, nx[k].f.x, ny[k].f.x);
            }
        }

        // rotate pipeline registers
        x4 = nx4; y4 = ny4;
        d0 = e0; d1 = e1; d2 = e2; d3 = e3;
    }

    float acc = (acc01.f.x + acc01.f.y) + (acc23.f.x + acc23.f.y) + acc_s;

    #pragma unroll
    for (int o = 16; o > 0; o >>= 1)
        acc += __shfl_down_sync(0xffffffffu, acc, o);

    __shared__ float warpsum[THREADS / 32];
    const int lane = threadIdx.x & 31;
    const int wid  = threadIdx.x >> 5;
    if (lane == 0) warpsum[wid] = acc;
    __syncthreads();

    __shared__ bool is_last;
    if (threadIdx.x == 0) {
        float v = 0.0f;
        #pragma unroll
        for (int w = 0; w < THREADS / 32; w++) v += warpsum[w];
        g_partials[blockIdx.x] = v;
        __threadfence();
        unsigned int prev = atomicAdd(&g_count, 1u);
        is_last = (prev == NUM_BLOCKS - 1);
    }
    __syncthreads();

    if (is_last) {
        __shared__ double s[THREADS];
        double t = 0.0;
        #pragma unroll
        for (int k = 0; k < NUM_BLOCKS / THREADS; k++)
            t += (double)g_partials[threadIdx.x * (NUM_BLOCKS / THREADS) + k];
        s[threadIdx.x] = t;
        __syncthreads();
        #pragma unroll
        for (int o = THREADS / 2; o > 0; o >>= 1) {
            if ((int)threadIdx.x < o) s[threadIdx.x] += s[threadIdx.x + o];
            __syncthreads();
        }
        if (threadIdx.x == 0) {
            out[0] = (float)s[0];
            g_count = 0;                 // reset for next graph replay
        }
    }
}

extern "C" void kernel_launch(void* const* d_in, const int* in_sizes, int n_in,
                              void* d_out, int out_size) {
    const float* a = (const float*)d_in[0];
    const float* b = (const float*)d_in[1];
    const float2* pos2;
    const float*  dist;
    if (in_sizes[0] < in_sizes[1]) { pos2 = (const float2*)a; dist = b; }
    else                           { pos2 = (const float2*)b; dist = a; }

    soa_kernel<<<N / 256, 256>>>(pos2);
    stress_kernel<<<NUM_BLOCKS, THREADS>>>(pos2, dist, (float*)d_out);
}